// round 15
// baseline (speedup 1.0000x reference)
#include <cuda_runtime.h>
#include <math.h>

#define Bb 4
#define Ll 4096
#define Hh 1024
#define Mm 4096          // complex FFT size (packs 8192 reals)
#define KPSTRIDE 2056    // float4 per head: (K[k], K[M-k]) for k=0..2048, padded

__device__ __align__(16) float g_xt[(size_t)Bb * Hh * Ll];
__device__ __align__(16) float4 g_KP[(size_t)Hh * KPSTRIDE];
__device__ __align__(16) float4 g_TW1[512];   // (w8.x, w8.y, w64.x, w64.y)
__device__ __align__(16) float4 g_TW2[512];   // (w512.x, w512.y, uc, us)

__device__ __forceinline__ int pad16(int i) { return i + (i >> 4); }
// XOR layout for the Ns=8 exchange: conflict-free on both its scatter and gather
__device__ __forceinline__ int sxor8(int i) { return i ^ (((i >> 6) & 1) << 3); }
#define SBUF_N 4352                    // > pad16(4095)+1 = 4351
#define DSMEM_BYTES (2 * SBUF_N * 8)   // kmain: two float2 buffers (double-buffered)

__device__ __forceinline__ float2 cadd(float2 a, float2 b) { return make_float2(a.x + b.x, a.y + b.y); }
__device__ __forceinline__ float2 csub(float2 a, float2 b) { return make_float2(a.x - b.x, a.y - b.y); }
__device__ __forceinline__ float2 cmul(float2 a, float2 b) {
    return make_float2(a.x * b.x - a.y * b.y, a.x * b.y + a.y * b.x);
}

// ---------- packed f32x2 helpers (sm_103a) ----------
typedef unsigned long long p2;
__device__ __forceinline__ p2 pkf(float2 a) {
    p2 r; asm("mov.b64 %0, {%1, %2};" : "=l"(r) : "f"(a.x), "f"(a.y)); return r;
}
__device__ __forceinline__ float2 upk(p2 a) {
    float2 r; asm("mov.b64 {%0, %1}, %2;" : "=f"(r.x), "=f"(r.y) : "l"(a)); return r;
}
__device__ __forceinline__ p2 padd(p2 a, p2 b) {
    p2 r; asm("add.rn.f32x2 %0, %1, %2;" : "=l"(r) : "l"(a), "l"(b)); return r;
}
// a - b  ==  fma(b, (-1,-1), a)   (exact)
__device__ __forceinline__ p2 psub(p2 a, p2 b, p2 n1) {
    p2 r; asm("fma.rn.f32x2 %0, %1, %2, %3;" : "=l"(r) : "l"(b), "l"(n1), "l"(a)); return r;
}
__device__ __forceinline__ p2 negone2() {
    p2 r; asm("mov.b64 %0, 0xBF800000BF800000;" : "=l"(r)); return r;
}

// mixed packed/scalar tail of the radix-8 butterfly
__device__ __forceinline__ void fft8_tailp(float2 v[8],
        p2 E0, p2 E2, float2 E1, float2 E3,
        p2 O0, p2 O2, float2 O1, float2 O3, p2 n1) {
    const float s = 0.70710678118654752440f;
    float2 W1 = make_float2(s * (O1.x + O1.y), s * (O1.y - O1.x));
    float2 W3 = make_float2(s * (O3.y - O3.x), -s * (O3.x + O3.y));
    v[0] = upk(padd(E0, O0)); v[4] = upk(psub(E0, O0, n1));
    float2 E2f = upk(E2), O2f = upk(O2);
    v[2] = make_float2(E2f.x + O2f.y, E2f.y - O2f.x);   // E2 + (-i)O2
    v[6] = make_float2(E2f.x - O2f.y, E2f.y + O2f.x);
    v[1] = cadd(E1, W1); v[5] = csub(E1, W1);
    v[3] = cadd(E3, W3); v[7] = csub(E3, W3);
}

__device__ __forceinline__ void fft8(float2 v[8], p2 n1) {
    p2 a0 = pkf(v[0]), a1 = pkf(v[1]), a2 = pkf(v[2]), a3 = pkf(v[3]);
    p2 a4 = pkf(v[4]), a5 = pkf(v[5]), a6 = pkf(v[6]), a7 = pkf(v[7]);
    p2 e0a = padd(a0, a4), e0b = psub(a0, a4, n1);
    p2 e1a = padd(a2, a6), e1b = psub(a2, a6, n1);
    p2 o0a = padd(a1, a5), o0b = psub(a1, a5, n1);
    p2 o1a = padd(a3, a7), o1b = psub(a3, a7, n1);
    p2 E0 = padd(e0a, e1a), E2 = psub(e0a, e1a, n1);
    p2 O0 = padd(o0a, o1a), O2 = psub(o0a, o1a, n1);
    float2 f0 = upk(e0b), f1 = upk(e1b), g0 = upk(o0b), g1 = upk(o1b);
    float2 E1 = make_float2(f0.x + f1.y, f0.y - f1.x);   // e0b + (-i)e1b
    float2 E3 = make_float2(f0.x - f1.y, f0.y + f1.x);
    float2 O1 = make_float2(g0.x + g1.y, g0.y - g1.x);
    float2 O3 = make_float2(g0.x - g1.y, g0.y + g1.x);
    fft8_tailp(v, E0, E2, E1, E3, O0, O2, O1, O3, n1);
}

// radix-8 butterfly with v[4..7] == 0 (zero-padded input, first pass only)
__device__ __forceinline__ void fft8h(float2 v[8], p2 n1) {
    p2 a0 = pkf(v[0]), a1 = pkf(v[1]), a2 = pkf(v[2]), a3 = pkf(v[3]);
    p2 E0 = padd(a0, a2), E2 = psub(a0, a2, n1);
    p2 O0 = padd(a1, a3), O2 = psub(a1, a3, n1);
    float2 E1 = make_float2(v[0].x + v[2].y, v[0].y - v[2].x);
    float2 E3 = make_float2(v[0].x - v[2].y, v[0].y + v[2].x);
    float2 O1 = make_float2(v[1].x + v[3].y, v[1].y - v[3].x);
    float2 O3 = make_float2(v[1].x - v[3].y, v[1].y + v[3].x);
    fft8_tailp(v, E0, E2, E1, E3, O0, O2, O1, O3, n1);
}

template <int Ns>
__device__ __forceinline__ float2 tw_base(int t) {
    int j = t & (Ns - 1);
    float sn, cs;
    sincospif((float)j * (1.0f / (4.0f * (float)Ns)), &sn, &cs);
    return make_float2(cs, -sn);
}

// tree-structured twiddle: depth 3 instead of 6
__device__ __forceinline__ void twiddle8(float2 v[8], float2 w1) {
    float2 w2 = cmul(w1, w1);
    float2 w3 = cmul(w2, w1);
    float2 w4 = cmul(w2, w2);
    float2 w5 = cmul(w3, w2);
    float2 w6 = cmul(w3, w3);
    float2 w7 = cmul(w4, w3);
    v[1] = cmul(v[1], w1); v[2] = cmul(v[2], w2); v[3] = cmul(v[3], w3);
    v[4] = cmul(v[4], w4); v[5] = cmul(v[5], w5); v[6] = cmul(v[6], w6);
    v[7] = cmul(v[7], w7);
}

// ---- single-buffer exchange (trailing barrier) — kfront, small static smem ----
template <int Ns>
__device__ __forceinline__ void exch_sb(float2 v[8], int t, float2* s) {
    int idxD = ((t & ~(Ns - 1)) << 3) | (t & (Ns - 1));
#pragma unroll
    for (int r = 0; r < 8; ++r) s[pad16(idxD + r * Ns)] = v[r];
    __syncthreads();
#pragma unroll
    for (int r = 0; r < 8; ++r) v[r] = s[pad16(t + (r << 9))];
    __syncthreads();
}

__device__ __forceinline__ void exch8x_sb(float2 v[8], int t, float2* s) {
    int idxD = ((t & ~7) << 3) | (t & 7);
#pragma unroll
    for (int r = 0; r < 8; ++r) s[sxor8(idxD + r * 8)] = v[r];
    __syncthreads();
#pragma unroll
    for (int r = 0; r < 8; ++r) v[r] = s[sxor8(t + (r << 9))];
    __syncthreads();
}

__device__ __forceinline__ void fft4096_sb(float2 v[8], int t, float2* s,
                                           float2 w8, float2 w64, float2 w512,
                                           bool halfzero, p2 n1) {
    if (halfzero) fft8h(v, n1); else fft8(v, n1);
    exch_sb<1>(v, t, s);
    twiddle8(v, w8);  fft8(v, n1); exch8x_sb(v, t, s);
    twiddle8(v, w64); fft8(v, n1); exch_sb<64>(v, t, s);
    twiddle8(v, w512); fft8(v, n1);
}

// ---- double-buffered exchange (one barrier) — kmain ----
template <int Ns>
__device__ __forceinline__ void exch_db(float2 v[8], int t, float2* s) {
    int idxD = ((t & ~(Ns - 1)) << 3) | (t & (Ns - 1));
#pragma unroll
    for (int r = 0; r < 8; ++r) s[pad16(idxD + r * Ns)] = v[r];
    __syncthreads();
#pragma unroll
    for (int r = 0; r < 8; ++r) v[r] = s[pad16(t + (r << 9))];
}

__device__ __forceinline__ void exch8x_db(float2 v[8], int t, float2* s) {
    int idxD = ((t & ~7) << 3) | (t & 7);
#pragma unroll
    for (int r = 0; r < 8; ++r) s[sxor8(idxD + r * 8)] = v[r];
    __syncthreads();
#pragma unroll
    for (int r = 0; r < 8; ++r) v[r] = s[sxor8(t + (r << 9))];
}

// 4096-pt FFT, double-buffered (3 barriers). Buffers: s0, s1, s0.
__device__ __forceinline__ void fft4096_reg(float2 v[8], int t, float2* s0, float2* s1,
                                            float2 w8, float2 w64, float2 w512,
                                            bool halfzero, p2 n1) {
    if (halfzero) fft8h(v, n1); else fft8(v, n1);
    exch_db<1>(v, t, s0);
    twiddle8(v, w8);  fft8(v, n1); exch8x_db(v, t, s1);
    twiddle8(v, w64); fft8(v, n1); exch_db<64>(v, t, s0);
    twiddle8(v, w512); fft8(v, n1);
}

// untangle pair (Zk, Zm) at frequency k -> multiply by (Kk, Km) -> retangle.
__device__ __forceinline__ float2 conv_pair(float2 Zk, float2 Zm, float uc, float us,
                                            float4 kp, float2* Cm) {
    float2 Fe = make_float2(0.5f * (Zk.x + Zm.x), 0.5f * (Zk.y - Zm.y));
    float2 Fo = make_float2(0.5f * (Zk.y + Zm.y), -0.5f * (Zk.x - Zm.x));
    float2 P = make_float2(uc * Fo.x + us * Fo.y, uc * Fo.y - us * Fo.x);  // (uc,-us)*Fo
    float2 Ak = cadd(Fe, P);
    float2 Am = make_float2(Fe.x - P.x, -(Fe.y - P.y));
    float2 Yk = cmul(Ak, make_float2(kp.x, kp.y));
    float2 Ym = cmul(Am, make_float2(kp.z, kp.w));
    float2 Ge = make_float2(0.5f * (Yk.x + Ym.x), 0.5f * (Yk.y - Ym.y));
    float2 d2 = make_float2(0.5f * (Yk.x - Ym.x), 0.5f * (Yk.y + Ym.y));
    float2 Go = make_float2(uc * d2.x - us * d2.y, uc * d2.y + us * d2.x);  // (uc,us)*d2
    *Cm = make_float2(Ge.x + Go.y, Ge.y - Go.x);
    return make_float2(Ge.x - Go.y, -(Ge.y + Go.x));
}

// K-spectrum untangle -> write (K[k], K[M-k]) pair
__device__ __forceinline__ void kspec_step(int k, float uc, float us,
                                           const float2* s, float4* __restrict__ outp) {
    int km = (Mm - k) & (Mm - 1);
    float2 Zk = s[pad16(k)];
    float2 Zm = s[pad16(km)];
    float2 Fe = make_float2(0.5f * (Zk.x + Zm.x), 0.5f * (Zk.y - Zm.y));
    float2 Fo = make_float2(0.5f * (Zk.y + Zm.y), -0.5f * (Zk.x - Zm.x));
    float2 P = make_float2(uc * Fo.x + us * Fo.y, uc * Fo.y - us * Fo.x);
    float2 Ak = cadd(Fe, P);
    float2 Am = make_float2(Fe.x - P.x, -(Fe.y - P.y));
    outp[k] = make_float4(Ak.x, Ak.y, Am.x, Am.y);
}

// ---- 64x64 float4 transpose tile with XOR swizzle (scalar phase 2 — kfront) ----
__device__ __forceinline__ void trans_tile(const float* __restrict__ src, float* __restrict__ dst,
                                           int ldS, int ldD, int r0, int c0,
                                           int u, int step, float4* tile) {
    int c = u & 15;
    for (int l = u >> 4; l < 64; l += step) {
        const float4* p = (const float4*)(src + (size_t)(r0 + l) * ldS + c0) + c;
        tile[l * 16 + (c ^ (l >> 2))] = *p;
    }
    __syncthreads();
    const float* ts = (const float*)tile;
    int l4 = u & 15;
    for (int h = u >> 4; h < 64; h += step) {
        int col = (h >> 2) ^ l4;
        int base = l4 * 64;
        float4 o;
        o.x = ts[(base + col) * 4 + (h & 3)];
        o.y = ts[(base + 16 + col) * 4 + (h & 3)];
        o.z = ts[(base + 32 + col) * 4 + (h & 3)];
        o.w = ts[(base + 48 + col) * 4 + (h & 3)];
        *((float4*)(dst + (size_t)(c0 + h) * ldD + r0) + l4) = o;
    }
}

// rotation by pi/8 (k advances by 512): exact constant-angle recurrence
#define C8 0.92387953251128675613f
#define S8 0.38268343236508977173f

// ---------------- Kernel 1: K-spectrum pairs + input transpose + TW table ----------------
__global__ void __launch_bounds__(512, 4) kfront(const float* __restrict__ x,
                                                 const float* __restrict__ kin) {
    __shared__ __align__(16) float2 sbuf[SBUF_N];
    int t = threadIdx.x;
    if (blockIdx.x < Hh) {
        int h = blockIdx.x;
        p2 n1 = negone2();
        float2 w8 = tw_base<8>(t), w64 = tw_base<64>(t), w512 = tw_base<512>(t);
        float us, uc;
        sincospif((float)t * (1.0f / 4096.0f), &us, &uc);
        // block 0 publishes the per-thread twiddle table for kmain (launch ordering)
        if (h == 0) {
            g_TW1[t] = make_float4(w8.x, w8.y, w64.x, w64.y);
            g_TW2[t] = make_float4(w512.x, w512.y, uc, us);
        }
        const float2* row = (const float2*)(kin + (size_t)h * Ll);
        float2 v[8];
#pragma unroll
        for (int r = 0; r < 4; ++r) {
            float2 a = row[t + (r << 9)];
            a.x = copysignf(fmaxf(fabsf(a.x) - 0.1f, 0.0f), a.x);
            a.y = copysignf(fmaxf(fabsf(a.y) - 0.1f, 0.0f), a.y);
            v[r] = a;
        }
#pragma unroll
        for (int r = 4; r < 8; ++r) v[r] = make_float2(0.0f, 0.0f);
        fft4096_sb(v, t, sbuf, w8, w64, w512, true, n1);
#pragma unroll
        for (int r = 0; r < 8; ++r) sbuf[pad16(t + (r << 9))] = v[r];
        __syncthreads();
        float4* outp = g_KP + (size_t)h * KPSTRIDE;
#pragma unroll
        for (int i = 0; i < 4; ++i) {
            kspec_step(t + (i << 9), uc, us, sbuf, outp);
            float nc = uc * C8 - us * S8;           // rotate angle by +pi/8
            us = us * C8 + uc * S8;
            uc = nc;
        }
        if (t == 0) kspec_step(2048, 0.0f, 1.0f, sbuf, outp);
    } else {
        int bid = blockIdx.x - Hh;
        int b = bid >> 10;
        int rem = bid & 1023;
        int l0 = (rem >> 4) << 6;
        int h0 = (rem & 15) << 6;
        float4* tile = (float4*)sbuf;      // alias 16KB of the FFT scratch
        trans_tile(x + (size_t)b * Ll * Hh, g_xt + (size_t)b * Hh * Ll,
                   Hh, Ll, l0, h0, t, 32, tile);
    }
}

// ---------------- Kernel 2: per-(b,h) FFT conv, double-buffered, fused skip ----------------
__global__ void __launch_bounds__(512, 2) kmain(const float* __restrict__ Dv) {
    extern __shared__ __align__(16) float2 dynbuf[];
    float2* s0 = dynbuf;
    float2* s1 = dynbuf + SBUF_N;
    int row = blockIdx.x;            // b*H + h
    int h = row & (Hh - 1);
    int t = threadIdx.x;
    p2 n1 = negone2();
    float dh = __ldg(&Dv[h]);
    float4 tw1 = __ldg(&g_TW1[t]);
    float4 tw2 = __ldg(&g_TW2[t]);
    float2 w8 = make_float2(tw1.x, tw1.y), w64 = make_float2(tw1.z, tw1.w);
    float2 w512 = make_float2(tw2.x, tw2.y);
    const float4* KP = g_KP + (size_t)h * KPSTRIDE;
    float2* xrow = ((float2*)g_xt) + (size_t)row * (Ll / 2);

    float2 v[8];
#pragma unroll
    for (int r = 0; r < 4; ++r) v[r] = xrow[t + (r << 9)];   // z[n] = x[2n] + i x[2n+1]
#pragma unroll
    for (int r = 4; r < 8; ++r) v[r] = make_float2(0.0f, 0.0f);
    fft4096_reg(v, t, s0, s1, w8, w64, w512, true, n1);   // v[r] = Z[t + 512 r]

    // publish upper half (slots 2048..4095) + Z[0] into s1; s1's exch8x readers all
    // finished before the exch<64> barrier -> no extra barrier before these writes
#pragma unroll
    for (int r = 4; r < 8; ++r) s1[pad16(t + (r << 9))] = v[r];
    if (t == 0) s1[0] = v[0];
    __syncthreads();

    // middle: k = t + 512 i in [0,2047]; Zk in regs, Zm from s1 (read+write same thread)
    float uc = tw2.z, us = tw2.w;
#pragma unroll
    for (int i = 0; i < 4; ++i) {
        int k = t + (i << 9);
        int m = (Mm - k) & (Mm - 1);
        float2 Zm = s1[pad16(m)];
        float2 Cm;
        v[i] = conv_pair(v[i], Zm, uc, us, __ldg(&KP[k]), &Cm);
        if (k != 0) s1[pad16(m)] = Cm;        // m in 2049..4095 (k=0 self-pair skipped)
        float nc = uc * C8 - us * S8;         // rotate angle by +pi/8
        us = us * C8 + uc * S8;
        uc = nc;
    }
    if (t == 0) {                             // Nyquist k=2048: self-pair, own slot
        float2 Z = s1[pad16(2048)];
        float2 Cm;
        s1[pad16(2048)] = conv_pair(Z, Z, 0.0f, 1.0f, __ldg(&KP[2048]), &Cm);
    }
    __syncthreads();

    // gather upper half of C from s1; lower half already in v[0..3]. The inverse FFT's
    // first scatter goes to s0 (safe: s0's readers finished before the publish barrier)
#pragma unroll
    for (int r = 4; r < 8; ++r) v[r] = s1[pad16(t + (r << 9))];

    // inverse via conj trick: y-packed = conj(FFT(C))/M ; fuse D*x skip
    fft4096_reg(v, t, s0, s1, w8, w64, w512, false, n1);
    const float invM = 1.0f / 4096.0f;
#pragma unroll
    for (int r = 0; r < 4; ++r) {
        int p = t + (r << 9);
        float2 xv = xrow[p];
        xrow[p] = make_float2(fmaf(dh, xv.x, v[r].x * invM),
                              fmaf(dh, xv.y, -v[r].y * invM));
    }
}

// ---------------- Kernel 3: transpose yt -> out, 4x4 register-transpose phase 2 ----------------
// Phase 2: 256 tasks (r4 = u&15 fast, c = u>>4). Task loads 4x LDS.128 from tile rows
// 4r4..4r4+3 at swizzled col (c ^ r4)  [l>>2 == r4 for all 4 rows -> same col], then
// 4 coalesced STG.128. Banks: addr mod 32 = 4(c^r4) -> distinct per 8-lane phase.
__global__ void __launch_bounds__(256) ktrans_out(float* __restrict__ out) {
    __shared__ __align__(16) float4 tile[1024];
    int b = blockIdx.z;
    int h0 = blockIdx.x << 6, l0 = blockIdx.y << 6;
    const float* src = g_xt + (size_t)b * Hh * Ll;
    float* dst = out + (size_t)b * Ll * Hh;
    int u = threadIdx.x;
    int cc = u & 15;
    for (int l = u >> 4; l < 64; l += 16)
        tile[l * 16 + (cc ^ (l >> 2))] = *((const float4*)(src + (size_t)(h0 + l) * Ll + l0) + cc);
    __syncthreads();
    int r4 = u & 15, c = u >> 4;
    int col = c ^ r4;
    float4 a = tile[(4 * r4 + 0) * 16 + col];
    float4 bq = tile[(4 * r4 + 1) * 16 + col];
    float4 d = tile[(4 * r4 + 2) * 16 + col];
    float4 e = tile[(4 * r4 + 3) * 16 + col];
    float* dbase = dst + (size_t)(l0 + 4 * c) * Hh + h0;
    ((float4*)(dbase))[r4]           = make_float4(a.x, bq.x, d.x, e.x);
    ((float4*)(dbase + Hh))[r4]      = make_float4(a.y, bq.y, d.y, e.y);
    ((float4*)(dbase + 2 * Hh))[r4]  = make_float4(a.z, bq.z, d.z, e.z);
    ((float4*)(dbase + 3 * Hh))[r4]  = make_float4(a.w, bq.w, d.w, e.w);
}

extern "C" void kernel_launch(void* const* d_in, const int* in_sizes, int n_in,
                              void* d_out, int out_size) {
    const float* x   = (const float*)d_in[0];
    const float* ker = (const float*)d_in[1];
    const float* Dv  = (const float*)d_in[2];
    for (int i = 0; i < n_in; ++i) {
        if (in_sizes[i] == Bb * Ll * Hh)      x   = (const float*)d_in[i];
        else if (in_sizes[i] == Hh * Ll)      ker = (const float*)d_in[i];
        else if (in_sizes[i] == Hh)           Dv  = (const float*)d_in[i];
    }
    cudaFuncSetAttribute(kmain, cudaFuncAttributeMaxDynamicSharedMemorySize, DSMEM_BYTES);
    kfront<<<Hh + (Bb * (Ll / 64) * (Hh / 64)), 512>>>(x, ker);
    kmain<<<Bb * Hh, 512, DSMEM_BYTES>>>(Dv);
    ktrans_out<<<dim3(Hh / 64, Ll / 64, Bb), 256>>>((float*)d_out);
}

// round 16
// speedup vs baseline: 1.0695x; 1.0695x over previous
#include <cuda_runtime.h>
#include <math.h>

#define Bb 4
#define Ll 4096
#define Hh 1024
#define Mm 4096          // complex FFT size (packs 8192 reals)
#define KPSTRIDE 2056    // float4 per head: (K[k], K[M-k]) for k=0..2048, padded

__device__ __align__(16) float g_xt[(size_t)Bb * Hh * Ll];
__device__ __align__(16) float4 g_KP[(size_t)Hh * KPSTRIDE];
__device__ __align__(16) float4 g_TW1[512];   // (w8.x, w8.y, w64.x, w64.y)
__device__ __align__(16) float4 g_TW2[512];   // (w512.x, w512.y, uc, us)

__device__ __forceinline__ int pad16(int i) { return i + (i >> 4); }
// XOR layout for the Ns=8 exchange: conflict-free on both its scatter and gather
__device__ __forceinline__ int sxor8(int i) { return i ^ (((i >> 6) & 1) << 3); }
#define SBUF_N 4352                    // > pad16(4095)+1 = 4351
#define DSMEM_BYTES (2 * SBUF_N * 8)   // kmain: two float2 buffers (double-buffered)

__device__ __forceinline__ float2 cadd(float2 a, float2 b) { return make_float2(a.x + b.x, a.y + b.y); }
__device__ __forceinline__ float2 csub(float2 a, float2 b) { return make_float2(a.x - b.x, a.y - b.y); }
__device__ __forceinline__ float2 cmul(float2 a, float2 b) {
    return make_float2(a.x * b.x - a.y * b.y, a.x * b.y + a.y * b.x);
}

// ---------- packed f32x2 helpers (sm_103a) ----------
typedef unsigned long long p2;
__device__ __forceinline__ p2 pkf(float2 a) {
    p2 r; asm("mov.b64 %0, {%1, %2};" : "=l"(r) : "f"(a.x), "f"(a.y)); return r;
}
__device__ __forceinline__ float2 upk(p2 a) {
    float2 r; asm("mov.b64 {%0, %1}, %2;" : "=f"(r.x), "=f"(r.y) : "l"(a)); return r;
}
__device__ __forceinline__ p2 padd(p2 a, p2 b) {
    p2 r; asm("add.rn.f32x2 %0, %1, %2;" : "=l"(r) : "l"(a), "l"(b)); return r;
}
// a - b  ==  fma(b, (-1,-1), a)   (exact)
__device__ __forceinline__ p2 psub(p2 a, p2 b, p2 n1) {
    p2 r; asm("fma.rn.f32x2 %0, %1, %2, %3;" : "=l"(r) : "l"(b), "l"(n1), "l"(a)); return r;
}
__device__ __forceinline__ p2 negone2() {
    p2 r; asm("mov.b64 %0, 0xBF800000BF800000;" : "=l"(r)); return r;
}

// mixed packed/scalar tail of the radix-8 butterfly
__device__ __forceinline__ void fft8_tailp(float2 v[8],
        p2 E0, p2 E2, float2 E1, float2 E3,
        p2 O0, p2 O2, float2 O1, float2 O3, p2 n1) {
    const float s = 0.70710678118654752440f;
    float2 W1 = make_float2(s * (O1.x + O1.y), s * (O1.y - O1.x));
    float2 W3 = make_float2(s * (O3.y - O3.x), -s * (O3.x + O3.y));
    v[0] = upk(padd(E0, O0)); v[4] = upk(psub(E0, O0, n1));
    float2 E2f = upk(E2), O2f = upk(O2);
    v[2] = make_float2(E2f.x + O2f.y, E2f.y - O2f.x);   // E2 + (-i)O2
    v[6] = make_float2(E2f.x - O2f.y, E2f.y + O2f.x);
    v[1] = cadd(E1, W1); v[5] = csub(E1, W1);
    v[3] = cadd(E3, W3); v[7] = csub(E3, W3);
}

__device__ __forceinline__ void fft8(float2 v[8], p2 n1) {
    p2 a0 = pkf(v[0]), a1 = pkf(v[1]), a2 = pkf(v[2]), a3 = pkf(v[3]);
    p2 a4 = pkf(v[4]), a5 = pkf(v[5]), a6 = pkf(v[6]), a7 = pkf(v[7]);
    p2 e0a = padd(a0, a4), e0b = psub(a0, a4, n1);
    p2 e1a = padd(a2, a6), e1b = psub(a2, a6, n1);
    p2 o0a = padd(a1, a5), o0b = psub(a1, a5, n1);
    p2 o1a = padd(a3, a7), o1b = psub(a3, a7, n1);
    p2 E0 = padd(e0a, e1a), E2 = psub(e0a, e1a, n1);
    p2 O0 = padd(o0a, o1a), O2 = psub(o0a, o1a, n1);
    float2 f0 = upk(e0b), f1 = upk(e1b), g0 = upk(o0b), g1 = upk(o1b);
    float2 E1 = make_float2(f0.x + f1.y, f0.y - f1.x);   // e0b + (-i)e1b
    float2 E3 = make_float2(f0.x - f1.y, f0.y + f1.x);
    float2 O1 = make_float2(g0.x + g1.y, g0.y - g1.x);
    float2 O3 = make_float2(g0.x - g1.y, g0.y + g1.x);
    fft8_tailp(v, E0, E2, E1, E3, O0, O2, O1, O3, n1);
}

// radix-8 butterfly with v[4..7] == 0 (zero-padded input, first pass only)
__device__ __forceinline__ void fft8h(float2 v[8], p2 n1) {
    p2 a0 = pkf(v[0]), a1 = pkf(v[1]), a2 = pkf(v[2]), a3 = pkf(v[3]);
    p2 E0 = padd(a0, a2), E2 = psub(a0, a2, n1);
    p2 O0 = padd(a1, a3), O2 = psub(a1, a3, n1);
    float2 E1 = make_float2(v[0].x + v[2].y, v[0].y - v[2].x);
    float2 E3 = make_float2(v[0].x - v[2].y, v[0].y + v[2].x);
    float2 O1 = make_float2(v[1].x + v[3].y, v[1].y - v[3].x);
    float2 O3 = make_float2(v[1].x - v[3].y, v[1].y + v[3].x);
    fft8_tailp(v, E0, E2, E1, E3, O0, O2, O1, O3, n1);
}

template <int Ns>
__device__ __forceinline__ float2 tw_base(int t) {
    int j = t & (Ns - 1);
    float sn, cs;
    sincospif((float)j * (1.0f / (4.0f * (float)Ns)), &sn, &cs);
    return make_float2(cs, -sn);
}

// tree-structured twiddle: depth 3 instead of 6
__device__ __forceinline__ void twiddle8(float2 v[8], float2 w1) {
    float2 w2 = cmul(w1, w1);
    float2 w3 = cmul(w2, w1);
    float2 w4 = cmul(w2, w2);
    float2 w5 = cmul(w3, w2);
    float2 w6 = cmul(w3, w3);
    float2 w7 = cmul(w4, w3);
    v[1] = cmul(v[1], w1); v[2] = cmul(v[2], w2); v[3] = cmul(v[3], w3);
    v[4] = cmul(v[4], w4); v[5] = cmul(v[5], w5); v[6] = cmul(v[6], w6);
    v[7] = cmul(v[7], w7);
}

// ---- single-buffer exchange (trailing barrier) — kfront, small static smem ----
template <int Ns>
__device__ __forceinline__ void exch_sb(float2 v[8], int t, float2* s) {
    int idxD = ((t & ~(Ns - 1)) << 3) | (t & (Ns - 1));
#pragma unroll
    for (int r = 0; r < 8; ++r) s[pad16(idxD + r * Ns)] = v[r];
    __syncthreads();
#pragma unroll
    for (int r = 0; r < 8; ++r) v[r] = s[pad16(t + (r << 9))];
    __syncthreads();
}

__device__ __forceinline__ void exch8x_sb(float2 v[8], int t, float2* s) {
    int idxD = ((t & ~7) << 3) | (t & 7);
#pragma unroll
    for (int r = 0; r < 8; ++r) s[sxor8(idxD + r * 8)] = v[r];
    __syncthreads();
#pragma unroll
    for (int r = 0; r < 8; ++r) v[r] = s[sxor8(t + (r << 9))];
    __syncthreads();
}

__device__ __forceinline__ void fft4096_sb(float2 v[8], int t, float2* s,
                                           float2 w8, float2 w64, float2 w512,
                                           bool halfzero, p2 n1) {
    if (halfzero) fft8h(v, n1); else fft8(v, n1);
    exch_sb<1>(v, t, s);
    twiddle8(v, w8);  fft8(v, n1); exch8x_sb(v, t, s);
    twiddle8(v, w64); fft8(v, n1); exch_sb<64>(v, t, s);
    twiddle8(v, w512); fft8(v, n1);
}

// ---- double-buffered exchange (one barrier) — kmain ----
template <int Ns>
__device__ __forceinline__ void exch_db(float2 v[8], int t, float2* s) {
    int idxD = ((t & ~(Ns - 1)) << 3) | (t & (Ns - 1));
#pragma unroll
    for (int r = 0; r < 8; ++r) s[pad16(idxD + r * Ns)] = v[r];
    __syncthreads();
#pragma unroll
    for (int r = 0; r < 8; ++r) v[r] = s[pad16(t + (r << 9))];
}

__device__ __forceinline__ void exch8x_db(float2 v[8], int t, float2* s) {
    int idxD = ((t & ~7) << 3) | (t & 7);
#pragma unroll
    for (int r = 0; r < 8; ++r) s[sxor8(idxD + r * 8)] = v[r];
    __syncthreads();
#pragma unroll
    for (int r = 0; r < 8; ++r) v[r] = s[sxor8(t + (r << 9))];
}

// 4096-pt FFT, double-buffered (3 barriers). Buffers: s0, s1, s0.
__device__ __forceinline__ void fft4096_reg(float2 v[8], int t, float2* s0, float2* s1,
                                            float2 w8, float2 w64, float2 w512,
                                            bool halfzero, p2 n1) {
    if (halfzero) fft8h(v, n1); else fft8(v, n1);
    exch_db<1>(v, t, s0);
    twiddle8(v, w8);  fft8(v, n1); exch8x_db(v, t, s1);
    twiddle8(v, w64); fft8(v, n1); exch_db<64>(v, t, s0);
    twiddle8(v, w512); fft8(v, n1);
}

// untangle pair (Zk, Zm) at frequency k -> multiply by (Kk, Km) -> retangle.
__device__ __forceinline__ float2 conv_pair(float2 Zk, float2 Zm, float uc, float us,
                                            float4 kp, float2* Cm) {
    float2 Fe = make_float2(0.5f * (Zk.x + Zm.x), 0.5f * (Zk.y - Zm.y));
    float2 Fo = make_float2(0.5f * (Zk.y + Zm.y), -0.5f * (Zk.x - Zm.x));
    float2 P = make_float2(uc * Fo.x + us * Fo.y, uc * Fo.y - us * Fo.x);  // (uc,-us)*Fo
    float2 Ak = cadd(Fe, P);
    float2 Am = make_float2(Fe.x - P.x, -(Fe.y - P.y));
    float2 Yk = cmul(Ak, make_float2(kp.x, kp.y));
    float2 Ym = cmul(Am, make_float2(kp.z, kp.w));
    float2 Ge = make_float2(0.5f * (Yk.x + Ym.x), 0.5f * (Yk.y - Ym.y));
    float2 d2 = make_float2(0.5f * (Yk.x - Ym.x), 0.5f * (Yk.y + Ym.y));
    float2 Go = make_float2(uc * d2.x - us * d2.y, uc * d2.y + us * d2.x);  // (uc,us)*d2
    *Cm = make_float2(Ge.x + Go.y, Ge.y - Go.x);
    return make_float2(Ge.x - Go.y, -(Ge.y + Go.x));
}

// K-spectrum untangle -> write (K[k], K[M-k]) pair
__device__ __forceinline__ void kspec_step(int k, float uc, float us,
                                           const float2* s, float4* __restrict__ outp) {
    int km = (Mm - k) & (Mm - 1);
    float2 Zk = s[pad16(k)];
    float2 Zm = s[pad16(km)];
    float2 Fe = make_float2(0.5f * (Zk.x + Zm.x), 0.5f * (Zk.y - Zm.y));
    float2 Fo = make_float2(0.5f * (Zk.y + Zm.y), -0.5f * (Zk.x - Zm.x));
    float2 P = make_float2(uc * Fo.x + us * Fo.y, uc * Fo.y - us * Fo.x);
    float2 Ak = cadd(Fe, P);
    float2 Am = make_float2(Fe.x - P.x, -(Fe.y - P.y));
    outp[k] = make_float4(Ak.x, Ak.y, Am.x, Am.y);
}

// ---- 64x64 float4 transpose tile with XOR swizzle (scalar phase 2 — PROVEN fastest) ----
__device__ __forceinline__ void trans_tile(const float* __restrict__ src, float* __restrict__ dst,
                                           int ldS, int ldD, int r0, int c0,
                                           int u, int step, float4* tile) {
    int c = u & 15;
    for (int l = u >> 4; l < 64; l += step) {
        const float4* p = (const float4*)(src + (size_t)(r0 + l) * ldS + c0) + c;
        tile[l * 16 + (c ^ (l >> 2))] = *p;
    }
    __syncthreads();
    const float* ts = (const float*)tile;
    int l4 = u & 15;
    for (int h = u >> 4; h < 64; h += step) {
        int col = (h >> 2) ^ l4;
        int base = l4 * 64;
        float4 o;
        o.x = ts[(base + col) * 4 + (h & 3)];
        o.y = ts[(base + 16 + col) * 4 + (h & 3)];
        o.z = ts[(base + 32 + col) * 4 + (h & 3)];
        o.w = ts[(base + 48 + col) * 4 + (h & 3)];
        *((float4*)(dst + (size_t)(c0 + h) * ldD + r0) + l4) = o;
    }
}

// rotation by pi/8 (k advances by 512): exact constant-angle recurrence
#define C8 0.92387953251128675613f
#define S8 0.38268343236508977173f

// ---------------- Kernel 1: K-spectrum pairs (with D folded in) + input transpose ----------------
// Skip fusion via linearity: y = irfft(Xf*(Kf + D)) since rfft(D*delta_0) == D.
// So add D[h] to k_soft[h][0] BEFORE the K FFT; kmain needs no skip at all.
__global__ void __launch_bounds__(512, 4) kfront(const float* __restrict__ x,
                                                 const float* __restrict__ kin,
                                                 const float* __restrict__ Dv) {
    __shared__ __align__(16) float2 sbuf[SBUF_N];
    int t = threadIdx.x;
    if (blockIdx.x < Hh) {
        int h = blockIdx.x;
        p2 n1 = negone2();
        float2 w8 = tw_base<8>(t), w64 = tw_base<64>(t), w512 = tw_base<512>(t);
        float us, uc;
        sincospif((float)t * (1.0f / 4096.0f), &us, &uc);
        // block 0 publishes the per-thread twiddle table for kmain (launch ordering)
        if (h == 0) {
            g_TW1[t] = make_float4(w8.x, w8.y, w64.x, w64.y);
            g_TW2[t] = make_float4(w512.x, w512.y, uc, us);
        }
        const float2* row = (const float2*)(kin + (size_t)h * Ll);
        float2 v[8];
#pragma unroll
        for (int r = 0; r < 4; ++r) {
            float2 a = row[t + (r << 9)];
            a.x = copysignf(fmaxf(fabsf(a.x) - 0.1f, 0.0f), a.x);
            a.y = copysignf(fmaxf(fabsf(a.y) - 0.1f, 0.0f), a.y);
            v[r] = a;
        }
#pragma unroll
        for (int r = 4; r < 8; ++r) v[r] = make_float2(0.0f, 0.0f);
        if (t == 0) v[0].x += __ldg(&Dv[h]);   // k'[0] = k_soft[0] + D[h]  (delta fold)
        fft4096_sb(v, t, sbuf, w8, w64, w512, true, n1);
#pragma unroll
        for (int r = 0; r < 8; ++r) sbuf[pad16(t + (r << 9))] = v[r];
        __syncthreads();
        float4* outp = g_KP + (size_t)h * KPSTRIDE;
#pragma unroll
        for (int i = 0; i < 4; ++i) {
            kspec_step(t + (i << 9), uc, us, sbuf, outp);
            float nc = uc * C8 - us * S8;           // rotate angle by +pi/8
            us = us * C8 + uc * S8;
            uc = nc;
        }
        if (t == 0) kspec_step(2048, 0.0f, 1.0f, sbuf, outp);
    } else {
        int bid = blockIdx.x - Hh;
        int b = bid >> 10;
        int rem = bid & 1023;
        int l0 = (rem >> 4) << 6;
        int h0 = (rem & 15) << 6;
        float4* tile = (float4*)sbuf;      // alias 16KB of the FFT scratch
        trans_tile(x + (size_t)b * Ll * Hh, g_xt + (size_t)b * Hh * Ll,
                   Hh, Ll, l0, h0, t, 32, tile);
    }
}

// ---------------- Kernel 2: per-(b,h) FFT conv, double-buffered (skip is in K) ----------------
__global__ void __launch_bounds__(512, 2) kmain() {
    extern __shared__ __align__(16) float2 dynbuf[];
    float2* s0 = dynbuf;
    float2* s1 = dynbuf + SBUF_N;
    int row = blockIdx.x;            // b*H + h
    int h = row & (Hh - 1);
    int t = threadIdx.x;
    p2 n1 = negone2();
    float4 tw1 = __ldg(&g_TW1[t]);
    float4 tw2 = __ldg(&g_TW2[t]);
    float2 w8 = make_float2(tw1.x, tw1.y), w64 = make_float2(tw1.z, tw1.w);
    float2 w512 = make_float2(tw2.x, tw2.y);
    const float4* KP = g_KP + (size_t)h * KPSTRIDE;
    float2* xrow = ((float2*)g_xt) + (size_t)row * (Ll / 2);

    float2 v[8];
#pragma unroll
    for (int r = 0; r < 4; ++r) v[r] = xrow[t + (r << 9)];   // z[n] = x[2n] + i x[2n+1]
#pragma unroll
    for (int r = 4; r < 8; ++r) v[r] = make_float2(0.0f, 0.0f);
    fft4096_reg(v, t, s0, s1, w8, w64, w512, true, n1);   // v[r] = Z[t + 512 r]

    // publish upper half (slots 2048..4095) + Z[0] into s1; s1's exch8x readers all
    // finished before the exch<64> barrier -> no extra barrier before these writes
#pragma unroll
    for (int r = 4; r < 8; ++r) s1[pad16(t + (r << 9))] = v[r];
    if (t == 0) s1[0] = v[0];
    __syncthreads();

    // middle: k = t + 512 i in [0,2047]; Zk in regs, Zm from s1 (read+write same thread)
    float uc = tw2.z, us = tw2.w;
#pragma unroll
    for (int i = 0; i < 4; ++i) {
        int k = t + (i << 9);
        int m = (Mm - k) & (Mm - 1);
        float2 Zm = s1[pad16(m)];
        float2 Cm;
        v[i] = conv_pair(v[i], Zm, uc, us, __ldg(&KP[k]), &Cm);
        if (k != 0) s1[pad16(m)] = Cm;        // m in 2049..4095 (k=0 self-pair skipped)
        float nc = uc * C8 - us * S8;         // rotate angle by +pi/8
        us = us * C8 + uc * S8;
        uc = nc;
    }
    if (t == 0) {                             // Nyquist k=2048: self-pair, own slot
        float2 Z = s1[pad16(2048)];
        float2 Cm;
        s1[pad16(2048)] = conv_pair(Z, Z, 0.0f, 1.0f, __ldg(&KP[2048]), &Cm);
    }
    __syncthreads();

    // gather upper half of C from s1; lower half already in v[0..3]. The inverse FFT's
    // first scatter goes to s0 (safe: s0's readers finished before the publish barrier)
#pragma unroll
    for (int r = 4; r < 8; ++r) v[r] = s1[pad16(t + (r << 9))];

    // inverse via conj trick: y-packed = conj(FFT(C))/M ; pure store (skip lives in K)
    fft4096_reg(v, t, s0, s1, w8, w64, w512, false, n1);
    const float invM = 1.0f / 4096.0f;
#pragma unroll
    for (int r = 0; r < 4; ++r) {
        int p = t + (r << 9);
        xrow[p] = make_float2(v[r].x * invM, -v[r].y * invM);
    }
}

// ---------------- Kernel 3: transpose yt [B,H,L] -> out [B,L,H] ----------------
__global__ void __launch_bounds__(256) ktrans_out(float* __restrict__ out) {
    __shared__ __align__(16) float4 tile[1024];
    int b = blockIdx.z;
    int h0 = blockIdx.x << 6, l0 = blockIdx.y << 6;
    trans_tile(g_xt + (size_t)b * Hh * Ll, out + (size_t)b * Ll * Hh,
               Ll, Hh, h0, l0, threadIdx.x, 16, tile);
}

extern "C" void kernel_launch(void* const* d_in, const int* in_sizes, int n_in,
                              void* d_out, int out_size) {
    const float* x   = (const float*)d_in[0];
    const float* ker = (const float*)d_in[1];
    const float* Dv  = (const float*)d_in[2];
    for (int i = 0; i < n_in; ++i) {
        if (in_sizes[i] == Bb * Ll * Hh)      x   = (const float*)d_in[i];
        else if (in_sizes[i] == Hh * Ll)      ker = (const float*)d_in[i];
        else if (in_sizes[i] == Hh)           Dv  = (const float*)d_in[i];
    }
    cudaFuncSetAttribute(kmain, cudaFuncAttributeMaxDynamicSharedMemorySize, DSMEM_BYTES);
    kfront<<<Hh + (Bb * (Ll / 64) * (Hh / 64)), 512>>>(x, ker, Dv);
    kmain<<<Bb * Hh, 512, DSMEM_BYTES>>>();
    ktrans_out<<<dim3(Hh / 64, Ll / 64, Bb), 256>>>((float*)d_out);
}

// round 17
// speedup vs baseline: 1.0753x; 1.0054x over previous
#include <cuda_runtime.h>
#include <math.h>

#define Bb 4
#define Ll 4096
#define Hh 1024
#define Mm 4096          // complex FFT size (packs 8192 reals)
#define KPSTRIDE 2056    // float4 per head: (K[k], K[M-k]) for k=0..2048, padded

__device__ __align__(16) float g_xt[(size_t)Bb * Hh * Ll];
__device__ __align__(16) float4 g_KP[(size_t)Hh * KPSTRIDE];
__device__ __align__(16) float4 g_TW1[512];   // (w8.x, w8.y, w64.x, w64.y)
__device__ __align__(16) float4 g_TW2[512];   // (w512.x, w512.y, uc, us)

__device__ __forceinline__ int pad16(int i) { return i + (i >> 4); }
// XOR layout for the Ns=8 exchange: conflict-free on both its scatter and gather
__device__ __forceinline__ int sxor8(int i) { return i ^ (((i >> 6) & 1) << 3); }
#define SBUF_N 4352                    // > pad16(4095)+1 = 4351
#define DSMEM_BYTES (2 * SBUF_N * 8)   // kmain: two float2 buffers (double-buffered)

__device__ __forceinline__ float2 cadd(float2 a, float2 b) { return make_float2(a.x + b.x, a.y + b.y); }
__device__ __forceinline__ float2 csub(float2 a, float2 b) { return make_float2(a.x - b.x, a.y - b.y); }
__device__ __forceinline__ float2 cmul(float2 a, float2 b) {
    return make_float2(a.x * b.x - a.y * b.y, a.x * b.y + a.y * b.x);
}

// ---------- packed f32x2 helpers (sm_103a) ----------
typedef unsigned long long p2;
__device__ __forceinline__ p2 pkf(float2 a) {
    p2 r; asm("mov.b64 %0, {%1, %2};" : "=l"(r) : "f"(a.x), "f"(a.y)); return r;
}
__device__ __forceinline__ float2 upk(p2 a) {
    float2 r; asm("mov.b64 {%0, %1}, %2;" : "=f"(r.x), "=f"(r.y) : "l"(a)); return r;
}
__device__ __forceinline__ p2 padd(p2 a, p2 b) {
    p2 r; asm("add.rn.f32x2 %0, %1, %2;" : "=l"(r) : "l"(a), "l"(b)); return r;
}
// a - b  ==  fma(b, (-1,-1), a)   (exact)
__device__ __forceinline__ p2 psub(p2 a, p2 b, p2 n1) {
    p2 r; asm("fma.rn.f32x2 %0, %1, %2, %3;" : "=l"(r) : "l"(b), "l"(n1), "l"(a)); return r;
}
__device__ __forceinline__ p2 negone2() {
    p2 r; asm("mov.b64 %0, 0xBF800000BF800000;" : "=l"(r)); return r;
}

// mixed packed/scalar tail of the radix-8 butterfly
__device__ __forceinline__ void fft8_tailp(float2 v[8],
        p2 E0, p2 E2, float2 E1, float2 E3,
        p2 O0, p2 O2, float2 O1, float2 O3, p2 n1) {
    const float s = 0.70710678118654752440f;
    float2 W1 = make_float2(s * (O1.x + O1.y), s * (O1.y - O1.x));
    float2 W3 = make_float2(s * (O3.y - O3.x), -s * (O3.x + O3.y));
    v[0] = upk(padd(E0, O0)); v[4] = upk(psub(E0, O0, n1));
    float2 E2f = upk(E2), O2f = upk(O2);
    v[2] = make_float2(E2f.x + O2f.y, E2f.y - O2f.x);   // E2 + (-i)O2
    v[6] = make_float2(E2f.x - O2f.y, E2f.y + O2f.x);
    v[1] = cadd(E1, W1); v[5] = csub(E1, W1);
    v[3] = cadd(E3, W3); v[7] = csub(E3, W3);
}

__device__ __forceinline__ void fft8(float2 v[8], p2 n1) {
    p2 a0 = pkf(v[0]), a1 = pkf(v[1]), a2 = pkf(v[2]), a3 = pkf(v[3]);
    p2 a4 = pkf(v[4]), a5 = pkf(v[5]), a6 = pkf(v[6]), a7 = pkf(v[7]);
    p2 e0a = padd(a0, a4), e0b = psub(a0, a4, n1);
    p2 e1a = padd(a2, a6), e1b = psub(a2, a6, n1);
    p2 o0a = padd(a1, a5), o0b = psub(a1, a5, n1);
    p2 o1a = padd(a3, a7), o1b = psub(a3, a7, n1);
    p2 E0 = padd(e0a, e1a), E2 = psub(e0a, e1a, n1);
    p2 O0 = padd(o0a, o1a), O2 = psub(o0a, o1a, n1);
    float2 f0 = upk(e0b), f1 = upk(e1b), g0 = upk(o0b), g1 = upk(o1b);
    float2 E1 = make_float2(f0.x + f1.y, f0.y - f1.x);   // e0b + (-i)e1b
    float2 E3 = make_float2(f0.x - f1.y, f0.y + f1.x);
    float2 O1 = make_float2(g0.x + g1.y, g0.y - g1.x);
    float2 O3 = make_float2(g0.x - g1.y, g0.y + g1.x);
    fft8_tailp(v, E0, E2, E1, E3, O0, O2, O1, O3, n1);
}

// radix-8 butterfly with v[4..7] == 0 (zero-padded input, first pass only)
__device__ __forceinline__ void fft8h(float2 v[8], p2 n1) {
    p2 a0 = pkf(v[0]), a1 = pkf(v[1]), a2 = pkf(v[2]), a3 = pkf(v[3]);
    p2 E0 = padd(a0, a2), E2 = psub(a0, a2, n1);
    p2 O0 = padd(a1, a3), O2 = psub(a1, a3, n1);
    float2 E1 = make_float2(v[0].x + v[2].y, v[0].y - v[2].x);
    float2 E3 = make_float2(v[0].x - v[2].y, v[0].y + v[2].x);
    float2 O1 = make_float2(v[1].x + v[3].y, v[1].y - v[3].x);
    float2 O3 = make_float2(v[1].x - v[3].y, v[1].y + v[3].x);
    fft8_tailp(v, E0, E2, E1, E3, O0, O2, O1, O3, n1);
}

template <int Ns>
__device__ __forceinline__ float2 tw_base(int t) {
    int j = t & (Ns - 1);
    float sn, cs;
    sincospif((float)j * (1.0f / (4.0f * (float)Ns)), &sn, &cs);
    return make_float2(cs, -sn);
}

// tree-structured twiddle: depth 3 instead of 6
__device__ __forceinline__ void twiddle8(float2 v[8], float2 w1) {
    float2 w2 = cmul(w1, w1);
    float2 w3 = cmul(w2, w1);
    float2 w4 = cmul(w2, w2);
    float2 w5 = cmul(w3, w2);
    float2 w6 = cmul(w3, w3);
    float2 w7 = cmul(w4, w3);
    v[1] = cmul(v[1], w1); v[2] = cmul(v[2], w2); v[3] = cmul(v[3], w3);
    v[4] = cmul(v[4], w4); v[5] = cmul(v[5], w5); v[6] = cmul(v[6], w6);
    v[7] = cmul(v[7], w7);
}

// ---- single-buffer exchange (trailing barrier) — kfront, small static smem ----
template <int Ns>
__device__ __forceinline__ void exch_sb(float2 v[8], int t, float2* s) {
    int idxD = ((t & ~(Ns - 1)) << 3) | (t & (Ns - 1));
#pragma unroll
    for (int r = 0; r < 8; ++r) s[pad16(idxD + r * Ns)] = v[r];
    __syncthreads();
#pragma unroll
    for (int r = 0; r < 8; ++r) v[r] = s[pad16(t + (r << 9))];
    __syncthreads();
}

__device__ __forceinline__ void exch8x_sb(float2 v[8], int t, float2* s) {
    int idxD = ((t & ~7) << 3) | (t & 7);
#pragma unroll
    for (int r = 0; r < 8; ++r) s[sxor8(idxD + r * 8)] = v[r];
    __syncthreads();
#pragma unroll
    for (int r = 0; r < 8; ++r) v[r] = s[sxor8(t + (r << 9))];
    __syncthreads();
}

__device__ __forceinline__ void fft4096_sb(float2 v[8], int t, float2* s,
                                           float2 w8, float2 w64, float2 w512,
                                           bool halfzero, p2 n1) {
    if (halfzero) fft8h(v, n1); else fft8(v, n1);
    exch_sb<1>(v, t, s);
    twiddle8(v, w8);  fft8(v, n1); exch8x_sb(v, t, s);
    twiddle8(v, w64); fft8(v, n1); exch_sb<64>(v, t, s);
    twiddle8(v, w512); fft8(v, n1);
}

// ---- double-buffered exchange (one barrier) — kmain ----
template <int Ns>
__device__ __forceinline__ void exch_db(float2 v[8], int t, float2* s) {
    int idxD = ((t & ~(Ns - 1)) << 3) | (t & (Ns - 1));
#pragma unroll
    for (int r = 0; r < 8; ++r) s[pad16(idxD + r * Ns)] = v[r];
    __syncthreads();
#pragma unroll
    for (int r = 0; r < 8; ++r) v[r] = s[pad16(t + (r << 9))];
}

__device__ __forceinline__ void exch8x_db(float2 v[8], int t, float2* s) {
    int idxD = ((t & ~7) << 3) | (t & 7);
#pragma unroll
    for (int r = 0; r < 8; ++r) s[sxor8(idxD + r * 8)] = v[r];
    __syncthreads();
#pragma unroll
    for (int r = 0; r < 8; ++r) v[r] = s[sxor8(t + (r << 9))];
}

// 4096-pt FFT, double-buffered (3 barriers). Buffers: s0, s1, s0.
__device__ __forceinline__ void fft4096_reg(float2 v[8], int t, float2* s0, float2* s1,
                                            float2 w8, float2 w64, float2 w512,
                                            bool halfzero, p2 n1) {
    if (halfzero) fft8h(v, n1); else fft8(v, n1);
    exch_db<1>(v, t, s0);
    twiddle8(v, w8);  fft8(v, n1); exch8x_db(v, t, s1);
    twiddle8(v, w64); fft8(v, n1); exch_db<64>(v, t, s0);
    twiddle8(v, w512); fft8(v, n1);
}

// untangle pair (Zk, Zm) at frequency k -> multiply by (Kk, Km) -> retangle.
__device__ __forceinline__ float2 conv_pair(float2 Zk, float2 Zm, float uc, float us,
                                            float4 kp, float2* Cm) {
    float2 Fe = make_float2(0.5f * (Zk.x + Zm.x), 0.5f * (Zk.y - Zm.y));
    float2 Fo = make_float2(0.5f * (Zk.y + Zm.y), -0.5f * (Zk.x - Zm.x));
    float2 P = make_float2(uc * Fo.x + us * Fo.y, uc * Fo.y - us * Fo.x);  // (uc,-us)*Fo
    float2 Ak = cadd(Fe, P);
    float2 Am = make_float2(Fe.x - P.x, -(Fe.y - P.y));
    float2 Yk = cmul(Ak, make_float2(kp.x, kp.y));
    float2 Ym = cmul(Am, make_float2(kp.z, kp.w));
    float2 Ge = make_float2(0.5f * (Yk.x + Ym.x), 0.5f * (Yk.y - Ym.y));
    float2 d2 = make_float2(0.5f * (Yk.x - Ym.x), 0.5f * (Yk.y + Ym.y));
    float2 Go = make_float2(uc * d2.x - us * d2.y, uc * d2.y + us * d2.x);  // (uc,us)*d2
    *Cm = make_float2(Ge.x + Go.y, Ge.y - Go.x);
    return make_float2(Ge.x - Go.y, -(Ge.y + Go.x));
}

// K-spectrum untangle -> write (K[k], K[M-k]) pair
__device__ __forceinline__ void kspec_step(int k, float uc, float us,
                                           const float2* s, float4* __restrict__ outp) {
    int km = (Mm - k) & (Mm - 1);
    float2 Zk = s[pad16(k)];
    float2 Zm = s[pad16(km)];
    float2 Fe = make_float2(0.5f * (Zk.x + Zm.x), 0.5f * (Zk.y - Zm.y));
    float2 Fo = make_float2(0.5f * (Zk.y + Zm.y), -0.5f * (Zk.x - Zm.x));
    float2 P = make_float2(uc * Fo.x + us * Fo.y, uc * Fo.y - us * Fo.x);
    float2 Ak = cadd(Fe, P);
    float2 Am = make_float2(Fe.x - P.x, -(Fe.y - P.y));
    outp[k] = make_float4(Ak.x, Ak.y, Am.x, Am.y);
}

// ---- 64x64 float4 transpose tile with XOR swizzle (scalar phase 2 — PROVEN fastest) ----
__device__ __forceinline__ void trans_tile(const float* __restrict__ src, float* __restrict__ dst,
                                           int ldS, int ldD, int r0, int c0,
                                           int u, int step, float4* tile) {
    int c = u & 15;
    for (int l = u >> 4; l < 64; l += step) {
        const float4* p = (const float4*)(src + (size_t)(r0 + l) * ldS + c0) + c;
        tile[l * 16 + (c ^ (l >> 2))] = *p;
    }
    __syncthreads();
    const float* ts = (const float*)tile;
    int l4 = u & 15;
    for (int h = u >> 4; h < 64; h += step) {
        int col = (h >> 2) ^ l4;
        int base = l4 * 64;
        float4 o;
        o.x = ts[(base + col) * 4 + (h & 3)];
        o.y = ts[(base + 16 + col) * 4 + (h & 3)];
        o.z = ts[(base + 32 + col) * 4 + (h & 3)];
        o.w = ts[(base + 48 + col) * 4 + (h & 3)];
        *((float4*)(dst + (size_t)(c0 + h) * ldD + r0) + l4) = o;
    }
}

// rotation by pi/8 (k advances by 512): exact constant-angle recurrence
#define C8 0.92387953251128675613f
#define S8 0.38268343236508977173f

// ---------------- Kernel 1: K-spectrum (D folded) + input transpose, ROLE-STRIPED ----------------
// Role striping: blockIdx % 5 == 0 -> FFT block (1024 of 5120); else transpose block.
// This interleaves compute-heavy FFT CTAs with DRAM-heavy transpose CTAs in every
// resident wave (contiguous role blocks previously ran as two serial phases).
__global__ void __launch_bounds__(512, 4) kfront(const float* __restrict__ x,
                                                 const float* __restrict__ kin,
                                                 const float* __restrict__ Dv) {
    __shared__ __align__(16) float2 sbuf[SBUF_N];
    int t = threadIdx.x;
    int bid = blockIdx.x;
    int q = bid / 5;
    if (bid - 5 * q == 0) {
        int h = q;                     // FFT role: h in 0..1023
        p2 n1 = negone2();
        float2 w8 = tw_base<8>(t), w64 = tw_base<64>(t), w512 = tw_base<512>(t);
        float us, uc;
        sincospif((float)t * (1.0f / 4096.0f), &us, &uc);
        // block h==0 publishes the per-thread twiddle table for kmain (launch ordering)
        if (h == 0) {
            g_TW1[t] = make_float4(w8.x, w8.y, w64.x, w64.y);
            g_TW2[t] = make_float4(w512.x, w512.y, uc, us);
        }
        const float2* row = (const float2*)(kin + (size_t)h * Ll);
        float2 v[8];
#pragma unroll
        for (int r = 0; r < 4; ++r) {
            float2 a = row[t + (r << 9)];
            a.x = copysignf(fmaxf(fabsf(a.x) - 0.1f, 0.0f), a.x);
            a.y = copysignf(fmaxf(fabsf(a.y) - 0.1f, 0.0f), a.y);
            v[r] = a;
        }
#pragma unroll
        for (int r = 4; r < 8; ++r) v[r] = make_float2(0.0f, 0.0f);
        if (t == 0) v[0].x += __ldg(&Dv[h]);   // k'[0] = k_soft[0] + D[h]  (delta fold)
        fft4096_sb(v, t, sbuf, w8, w64, w512, true, n1);
#pragma unroll
        for (int r = 0; r < 8; ++r) sbuf[pad16(t + (r << 9))] = v[r];
        __syncthreads();
        float4* outp = g_KP + (size_t)h * KPSTRIDE;
#pragma unroll
        for (int i = 0; i < 4; ++i) {
            kspec_step(t + (i << 9), uc, us, sbuf, outp);
            float nc = uc * C8 - us * S8;           // rotate angle by +pi/8
            us = us * C8 + uc * S8;
            uc = nc;
        }
        if (t == 0) kspec_step(2048, 0.0f, 1.0f, sbuf, outp);
    } else {
        int tid2 = bid - q - 1;        // transpose role: 0..4095 (bijective)
        int b = tid2 >> 10;
        int rem = tid2 & 1023;
        int l0 = (rem >> 4) << 6;
        int h0 = (rem & 15) << 6;
        float4* tile = (float4*)sbuf;      // alias 16KB of the FFT scratch
        trans_tile(x + (size_t)b * Ll * Hh, g_xt + (size_t)b * Hh * Ll,
                   Hh, Ll, l0, h0, t, 32, tile);
    }
}

// ---------------- Kernel 2: per-(b,h) FFT conv, double-buffered (skip is in K) ----------------
__global__ void __launch_bounds__(512, 2) kmain() {
    extern __shared__ __align__(16) float2 dynbuf[];
    float2* s0 = dynbuf;
    float2* s1 = dynbuf + SBUF_N;
    int row = blockIdx.x;            // b*H + h
    int h = row & (Hh - 1);
    int t = threadIdx.x;
    p2 n1 = negone2();
    float4 tw1 = __ldg(&g_TW1[t]);
    float4 tw2 = __ldg(&g_TW2[t]);
    float2 w8 = make_float2(tw1.x, tw1.y), w64 = make_float2(tw1.z, tw1.w);
    float2 w512 = make_float2(tw2.x, tw2.y);
    const float4* KP = g_KP + (size_t)h * KPSTRIDE;
    float2* xrow = ((float2*)g_xt) + (size_t)row * (Ll / 2);

    float2 v[8];
#pragma unroll
    for (int r = 0; r < 4; ++r) v[r] = xrow[t + (r << 9)];   // z[n] = x[2n] + i x[2n+1]
#pragma unroll
    for (int r = 4; r < 8; ++r) v[r] = make_float2(0.0f, 0.0f);
    fft4096_reg(v, t, s0, s1, w8, w64, w512, true, n1);   // v[r] = Z[t + 512 r]

    // publish upper half (slots 2048..4095) + Z[0] into s1; s1's exch8x readers all
    // finished before the exch<64> barrier -> no extra barrier before these writes
#pragma unroll
    for (int r = 4; r < 8; ++r) s1[pad16(t + (r << 9))] = v[r];
    if (t == 0) s1[0] = v[0];
    __syncthreads();

    // middle: k = t + 512 i in [0,2047]; Zk in regs, Zm from s1 (read+write same thread)
    float uc = tw2.z, us = tw2.w;
#pragma unroll
    for (int i = 0; i < 4; ++i) {
        int k = t + (i << 9);
        int m = (Mm - k) & (Mm - 1);
        float2 Zm = s1[pad16(m)];
        float2 Cm;
        v[i] = conv_pair(v[i], Zm, uc, us, __ldg(&KP[k]), &Cm);
        if (k != 0) s1[pad16(m)] = Cm;        // m in 2049..4095 (k=0 self-pair skipped)
        float nc = uc * C8 - us * S8;         // rotate angle by +pi/8
        us = us * C8 + uc * S8;
        uc = nc;
    }
    if (t == 0) {                             // Nyquist k=2048: self-pair, own slot
        float2 Z = s1[pad16(2048)];
        float2 Cm;
        s1[pad16(2048)] = conv_pair(Z, Z, 0.0f, 1.0f, __ldg(&KP[2048]), &Cm);
    }
    __syncthreads();

    // gather upper half of C from s1; lower half already in v[0..3]. The inverse FFT's
    // first scatter goes to s0 (safe: s0's readers finished before the publish barrier)
#pragma unroll
    for (int r = 4; r < 8; ++r) v[r] = s1[pad16(t + (r << 9))];

    // inverse via conj trick: y-packed = conj(FFT(C))/M ; pure store (skip lives in K)
    fft4096_reg(v, t, s0, s1, w8, w64, w512, false, n1);
    const float invM = 1.0f / 4096.0f;
#pragma unroll
    for (int r = 0; r < 4; ++r) {
        int p = t + (r << 9);
        xrow[p] = make_float2(v[r].x * invM, -v[r].y * invM);
    }
}

// ---------------- Kernel 3: transpose yt [B,H,L] -> out [B,L,H] ----------------
__global__ void __launch_bounds__(256) ktrans_out(float* __restrict__ out) {
    __shared__ __align__(16) float4 tile[1024];
    int b = blockIdx.z;
    int h0 = blockIdx.x << 6, l0 = blockIdx.y << 6;
    trans_tile(g_xt + (size_t)b * Hh * Ll, out + (size_t)b * Ll * Hh,
               Ll, Hh, h0, l0, threadIdx.x, 16, tile);
}

extern "C" void kernel_launch(void* const* d_in, const int* in_sizes, int n_in,
                              void* d_out, int out_size) {
    const float* x   = (const float*)d_in[0];
    const float* ker = (const float*)d_in[1];
    const float* Dv  = (const float*)d_in[2];
    for (int i = 0; i < n_in; ++i) {
        if (in_sizes[i] == Bb * Ll * Hh)      x   = (const float*)d_in[i];
        else if (in_sizes[i] == Hh * Ll)      ker = (const float*)d_in[i];
        else if (in_sizes[i] == Hh)           Dv  = (const float*)d_in[i];
    }
    cudaFuncSetAttribute(kmain, cudaFuncAttributeMaxDynamicSharedMemorySize, DSMEM_BYTES);
    kfront<<<Hh + (Bb * (Ll / 64) * (Hh / 64)), 512>>>(x, ker, Dv);
    kmain<<<Bb * Hh, 512, DSMEM_BYTES>>>();
    ktrans_out<<<dim3(Hh / 64, Ll / 64, Bb), 256>>>((float*)d_out);
}